// round 14
// baseline (speedup 1.0000x reference)
#include <cuda_runtime.h>

// GridToGraphConverter: B=4, C=16, H=W=512
//  out layout (float32, concatenated):
//   [0, NF)            node_features  (B*HW, C)
//   [NF, NF+E)         edge_index src row
//   [NF+E, NF+2E)      edge_index dst row
//   [NF+2E, NF+2E+2E)  edge_attr (E, 2)
//
// Two-kernel scheme exploiting |src-dst| symmetry, with K1 batch-split:
//  K1: grid 4096 = (half-row x batch). Each block accumulates its batch's
//      partial of the 4 DOWN/RIGHT direction sums (R, DL, D, DR) — only
//      own+down rows loaded (2x float4/plane), no smem, no barriers, no
//      inner batch loop (max MLP). Writes partials to a 16MB __device__
//      scratch + its batch's node_features slice directly.
//  K2: emits edge_index + edge_attr fully coalesced via the analytic
//      inverse edge->(col,slot) map; sums the 4 L2-resident partials;
//      up/left slots read the neighbor's down/right entry (symmetry).

#define Wd 512
#define Hd 512
#define HWd (Wd * Hd)
#define Cc 16
#define Bb 4
#define NFSZ (Bb * HWd * Cc)        // 16777216
#define Ed 2091012

// scratch: [b][h][k][col], k: 0=R, 1=DL, 2=D, 3=DR (each already /64)
__device__ float g_scr[Bb][Hd][4][Wd];

__global__ __launch_bounds__(256, 4) void g2g_k1(const float* __restrict__ grid,
                                                 float* __restrict__ out) {
    const int tid = threadIdx.x;
    const int rid = blockIdx.x & 1023;      // half-row id
    const int b = blockIdx.x >> 10;         // batch
    const int h = rid >> 1;                 // row
    const int half = rid & 1;               // half-row
    const int q = tid & 3;                  // channel quad id
    const int lane = tid & 31;
    const int wg = half * 256 + (tid & ~3); // first column of 4-node group
    const int n0 = h * Wd + wg;

    const bool hasDn = (h < Hd - 1);
    const bool hasL = (wg > 0);
    const bool hasR = (wg < Wd - 4);

    const int oDn = hasDn ? n0 + Wd : n0;   // clamped (garbage unread)
    const int oLd = hasL ? oDn - 1 : oDn;   // down-left fallback
    const int oRm = hasR ? n0 + 4 : n0;     // mid-right fallback
    const int oRd = hasR ? oDn + 4 : oDn;   // down-right fallback
    const bool leftLane = (lane < 4);
    const bool rightLane = (lane >= 28);

    float acc[4][4];                        // [node][k] k:0=R,1=DL,2=D,3=DR
#pragma unroll
    for (int i = 0; i < 4; i++)
#pragma unroll
        for (int k = 0; k < 4; k++) acc[i][k] = 0.0f;

    const float* pb = grid + (size_t)b * (Cc * HWd);
    float nf[4][4];
#pragma unroll
    for (int ci = 0; ci < 4; ci++) {
        const int c = q * 4 + ci;
        const float* p = pb + c * HWd;
        float4 ow = *(const float4*)(p + n0);
        float4 dn = *(const float4*)(p + oDn);
        nf[0][ci] = ow.x;
        nf[1][ci] = ow.y;
        nf[2][ci] = ow.z;
        nf[3][ci] = ow.w;

        // cross-group neighbor values (quad-stride shuffles; edge lanes
        // fall back to clamped global loads — works across blocks too)
        float mR = __shfl_down_sync(0xffffffffu, ow.x, 4);
        float dR = __shfl_down_sync(0xffffffffu, dn.x, 4);
        float dL = __shfl_up_sync(0xffffffffu, dn.w, 4);
        if (rightLane) {
            mR = p[oRm];
            dR = p[oRd];
        }
        if (leftLane) dL = p[oLd];

        // down/right sums only
        acc[0][0] += fabsf(ow.x - ow.y);
        acc[0][1] += fabsf(ow.x - dL);
        acc[0][2] += fabsf(ow.x - dn.x);
        acc[0][3] += fabsf(ow.x - dn.y);

        acc[1][0] += fabsf(ow.y - ow.z);
        acc[1][1] += fabsf(ow.y - dn.x);
        acc[1][2] += fabsf(ow.y - dn.y);
        acc[1][3] += fabsf(ow.y - dn.z);

        acc[2][0] += fabsf(ow.z - ow.w);
        acc[2][1] += fabsf(ow.z - dn.y);
        acc[2][2] += fabsf(ow.z - dn.z);
        acc[2][3] += fabsf(ow.z - dn.w);

        acc[3][0] += fabsf(ow.w - mR);
        acc[3][1] += fabsf(ow.w - dn.z);
        acc[3][2] += fabsf(ow.w - dn.w);
        acc[3][3] += fabsf(ow.w - dR);
    }
    // node_features store for this batch: node (n0+i), channels 4q..4q+3.
    float* dstb = out + (size_t)b * (HWd * Cc);
#pragma unroll
    for (int i = 0; i < 4; i++) {
        *(float4*)(dstb + (size_t)(n0 + i) * Cc + 4 * q) =
            make_float4(nf[i][0], nf[i][1], nf[i][2], nf[i][3]);
    }

    // Selective quad reduce: thread ends with node q's 4 sums (col = wg+q).
    const float inv64 = 1.0f / 64.0f;
    const int p1 = q & 1;
    float a[4];
#pragma unroll
    for (int k = 0; k < 4; k++) {
        float sA = p1 ? acc[0][k] : acc[1][k];
        float sB = p1 ? acc[2][k] : acc[3][k];
        float rA = __shfl_xor_sync(0xffffffffu, sA, 1);
        float rB = __shfl_xor_sync(0xffffffffu, sB, 1);
        float kA = (p1 ? acc[1][k] : acc[0][k]) + rA;
        float kB = (p1 ? acc[3][k] : acc[2][k]) + rB;
        float s2 = (q & 2) ? kA : kB;
        float r2 = __shfl_xor_sync(0xffffffffu, s2, 2);
        a[k] = (((q & 2) ? kB : kA) + r2) * inv64;
    }

    // Coalesced partial-scratch write: col = half*256 + tid.
    const int col = half * 256 + tid;
#pragma unroll
    for (int k = 0; k < 4; k++) g_scr[b][h][k][col] = a[k];
}

__global__ __launch_bounds__(256) void g2g_k2(float* __restrict__ out) {
    const int tid = threadIdx.x;
    const int h = blockIdx.x >> 1;
    const int half = blockIdx.x & 1;

    const float SQ2 = 1.41421356237309515f;
    float* eiS = out + NFSZ;
    float* eiD = out + NFSZ + Ed;
    float* ea  = out + NFSZ + 2 * Ed;

    const bool boundaryRow = (h == 0) || (h == Hd - 1);
    const int cnt = boundaryRow ? 1278 : 2045;
    const int rowBase = (h == 0) ? 0 : 2556 + (h - 1) * 4090;
    const int eBase = rowBase + half * cnt;

#pragma unroll
    for (int it = 0; it < 8; it++) {
        int le = it * 256 + tid;
        if (le >= cnt) break;
        int col_l, slot;
        if (!boundaryRow) {
            if (half == 0) {
                if (le < 5) {               // col 0: slots {1,2,4,6,7}
                    col_l = 0;
                    slot = (0x76421 >> (4 * le)) & 0xF;
                } else {
                    int j = le - 5;
                    col_l = 1 + (j >> 3);
                    slot = j & 7;
                }
            } else {
                if (le < 2040) {
                    col_l = le >> 3;
                    slot = le & 7;
                } else {                    // col 511: slots {0,1,3,5,6}
                    col_l = 255;
                    slot = (0x65310 >> (4 * (le - 2040))) & 0xF;
                }
            }
        } else if (h == 0) {                // slots 3..7 only
            if (half == 0) {
                if (le < 3) {               // col 0: {4,6,7}
                    col_l = 0;
                    slot = (le == 0) ? 4 : (le == 1) ? 6 : 7;
                } else {
                    int j = le - 3;
                    int d = j / 5;
                    col_l = 1 + d;
                    slot = 3 + (j - d * 5);
                }
            } else {
                if (le < 1275) {
                    int d = le / 5;
                    col_l = d;
                    slot = 3 + (le - d * 5);
                } else {                    // col 511: {3,5,6}
                    col_l = 255;
                    int r = le - 1275;
                    slot = (r == 0) ? 3 : (r == 1) ? 5 : 6;
                }
            }
        } else {                            // h == 511: slots 0..4 only
            if (half == 0) {
                if (le < 3) {               // col 0: {1,2,4}
                    col_l = 0;
                    slot = (le == 0) ? 1 : (le == 1) ? 2 : 4;
                } else {
                    int j = le - 3;
                    int d = j / 5;
                    col_l = 1 + d;
                    slot = j - d * 5;
                }
            } else {
                if (le < 1275) {
                    int d = le / 5;
                    col_l = d;
                    slot = le - d * 5;
                } else {                    // col 511: {0,1,3}
                    col_l = 255;
                    int r = le - 1275;
                    slot = (r == 0) ? 0 : (r == 1) ? 1 : 3;
                }
            }
        }

        int col = half * 256 + col_l;
        int dh = (slot < 3) ? -1 : ((slot >= 5) ? 1 : 0);
        int dw = ((0x42 >> slot) & 1) ? 0 : (((0x29 >> slot) & 1) ? -1 : 1);
        float ds = ((0xA5 >> slot) & 1) ? SQ2 : 1.0f;

        // symmetry map: up/left slots read the neighbor's down/right sum
        int sh, sk, sc;
        if (slot < 3) {         // UL,U,UR -> (h-1, {DR,D,DL}, col+slot-1)
            sh = h - 1;
            sk = 3 - slot;
            sc = col + slot - 1;
        } else if (slot == 3) { // L -> (h, R, col-1)
            sh = h;
            sk = 0;
            sc = col - 1;
        } else {                // R,DL,D,DR -> own entry
            sh = h;
            sk = slot - 4;
            sc = col;
        }
        float fd = (g_scr[0][sh][sk][sc] + g_scr[1][sh][sk][sc])
                 + (g_scr[2][sh][sk][sc] + g_scr[3][sh][sk][sc]);

        int nn = h * Wd + col;
        int e = eBase + le;
        eiS[e] = (float)nn;
        eiD[e] = (float)(nn + dh * Wd + dw);
        *(float2*)(ea + 2 * e) = make_float2(ds, fd);
    }
}

extern "C" void kernel_launch(void* const* d_in, const int* in_sizes, int n_in,
                              void* d_out, int out_size) {
    const float* grid = (const float*)d_in[0];
    float* out = (float*)d_out;
    // K1: 4096 blocks = 1024 half-rows x 4 batches
    g2g_k1<<<4096, 256>>>(grid, out);
    // K2: 1024 blocks emit edges
    g2g_k2<<<1024, 256>>>(out);
}